// round 1
// baseline (speedup 1.0000x reference)
#include <cuda_runtime.h>
#include <math.h>

#define NTOK   4096      // B*S = 2*2048
#define DIM    1024
#define NEXP   8
#define HIDDEN 4096

#define BM 128
#define BN 128
#define BK 8
#define NT 256

// ---------------- scratch (static __device__ — alloc-free) ----------------
__device__ int   g_cnt[NEXP];
__device__ int   g_list[NEXP][NTOK];      // packed token*2 + slot
__device__ float g_gw[NEXP][NTOK];        // gate weight aligned with list
__device__ float g_h[NTOK * 2 * HIDDEN];  // hidden activations per (token,slot)  (128 MiB)
__device__ float g_part[NTOK * 2 * DIM];  // per-slot output contribution          (32 MiB)

// ---------------- kernel 0: reset counters ----------------
__global__ void zero_cnt_kernel() {
    if (threadIdx.x < NEXP) g_cnt[threadIdx.x] = 0;
}

// ---------------- kernel 1: gating (1 warp per token) ----------------
__global__ void gate_kernel(const float* __restrict__ x,
                            const float* __restrict__ Wg,
                            const float* __restrict__ bg) {
    int warp = blockIdx.x * (blockDim.x >> 5) + (threadIdx.x >> 5);
    int lane = threadIdx.x & 31;
    if (warp >= NTOK) return;

    const float* xr = x + (size_t)warp * DIM;
    float acc[NEXP];
#pragma unroll
    for (int e = 0; e < NEXP; e++) acc[e] = 0.f;

    for (int d = lane; d < DIM; d += 32) {
        float xv = xr[d];
        const float4* w = reinterpret_cast<const float4*>(Wg + (size_t)d * NEXP);
        float4 w0 = w[0], w1 = w[1];
        acc[0] = fmaf(xv, w0.x, acc[0]);
        acc[1] = fmaf(xv, w0.y, acc[1]);
        acc[2] = fmaf(xv, w0.z, acc[2]);
        acc[3] = fmaf(xv, w0.w, acc[3]);
        acc[4] = fmaf(xv, w1.x, acc[4]);
        acc[5] = fmaf(xv, w1.y, acc[5]);
        acc[6] = fmaf(xv, w1.z, acc[6]);
        acc[7] = fmaf(xv, w1.w, acc[7]);
    }
#pragma unroll
    for (int off = 16; off > 0; off >>= 1) {
#pragma unroll
        for (int e = 0; e < NEXP; e++)
            acc[e] += __shfl_xor_sync(0xffffffffu, acc[e], off);
    }

    if (lane == 0) {
        float lg[NEXP];
        float mx = -1e30f;
#pragma unroll
        for (int e = 0; e < NEXP; e++) { lg[e] = acc[e] + bg[e]; mx = fmaxf(mx, lg[e]); }
        float p[NEXP];
        float s = 0.f;
#pragma unroll
        for (int e = 0; e < NEXP; e++) { p[e] = expf(lg[e] - mx); s += p[e]; }
        float inv = 1.f / s;

        // top-2 with lax.top_k tie semantics (lowest index wins ties)
        int i0 = 0;
#pragma unroll
        for (int e = 1; e < NEXP; e++) if (p[e] > p[i0]) i0 = e;
        int i1 = (i0 == 0) ? 1 : 0;
#pragma unroll
        for (int e = 0; e < NEXP; e++) if (e != i0 && p[e] > p[i1]) i1 = e;

        int pos0 = atomicAdd(&g_cnt[i0], 1);
        g_list[i0][pos0] = warp * 2 + 0;
        g_gw[i0][pos0]   = p[i0] * inv;
        int pos1 = atomicAdd(&g_cnt[i1], 1);
        g_list[i1][pos1] = warp * 2 + 1;
        g_gw[i1][pos1]   = p[i1] * inv;
    }
}

// ---------------- kernels 2/3: gathered expert GEMM ----------------
// MODE 0: A = gathered x rows,  W = W1[e] [K=DIM][N=HIDDEN], epilogue relu+b1 -> g_h
// MODE 1: A = gathered g_h rows, W = W2[e] [K=HIDDEN][N=DIM], epilogue gw*(.+b2) -> g_part
template<int MODE, int KDIM, int NCOLS>
__global__ __launch_bounds__(NT, 2)
void expert_ffn_gemm(const float* __restrict__ A_base,
                     const float* __restrict__ W,
                     const float* __restrict__ bias) {
    const int e   = blockIdx.z;
    const int cnt = g_cnt[e];
    const int m0  = blockIdx.x * BM;
    if (m0 >= cnt) return;

    __shared__ float As[BK][BM + 4];   // +4 pad: conflict-free transposed stores
    __shared__ float Bs[BK][BN];
    __shared__ int   s_row[BM];
    __shared__ float s_gw[BM];

    const int t = threadIdx.x;
    for (int i = t; i < BM; i += NT) {
        int r = m0 + i;
        if (r < cnt) { s_row[i] = g_list[e][r]; s_gw[i] = g_gw[e][r]; }
        else         { s_row[i] = -1;           s_gw[i] = 0.f; }
    }
    __syncthreads();

    // global loaders
    const int ar = t >> 1;            // 0..127
    const int ac = (t & 1) * 4;       // 0 or 4
    const int br = t >> 5;            // 0..7
    const int bc = (t & 31) * 4;      // 0..124

    const int prow = s_row[ar];
    const bool a_valid = (prow >= 0);
    const float* a_ptr;
    if (MODE == 0) a_ptr = A_base + (size_t)(prow >> 1) * DIM + ac;
    else           a_ptr = g_h + (size_t)prow * HIDDEN + ac;

    const int gn0 = blockIdx.y * BN;
    const float* b_ptr = W + (size_t)e * KDIM * NCOLS + (size_t)br * NCOLS + gn0 + bc;

    // compute mapping
    const int tx = t & 15;
    const int ty = t >> 4;

    float acc[8][8];
#pragma unroll
    for (int i = 0; i < 8; i++)
#pragma unroll
        for (int j = 0; j < 8; j++) acc[i][j] = 0.f;

    float4 a_reg = a_valid ? *(const float4*)a_ptr : make_float4(0.f, 0.f, 0.f, 0.f);
    float4 b_reg = *(const float4*)b_ptr;

    for (int k0 = 0; k0 < KDIM; k0 += BK) {
        As[ac + 0][ar] = a_reg.x;
        As[ac + 1][ar] = a_reg.y;
        As[ac + 2][ar] = a_reg.z;
        As[ac + 3][ar] = a_reg.w;
        *(float4*)&Bs[br][bc] = b_reg;
        __syncthreads();

        if (k0 + BK < KDIM) {
            a_reg = a_valid ? *(const float4*)(a_ptr + k0 + BK)
                            : make_float4(0.f, 0.f, 0.f, 0.f);
            b_reg = *(const float4*)(b_ptr + (size_t)(k0 + BK) * NCOLS);
        }

#pragma unroll
        for (int kk = 0; kk < BK; kk++) {
            float4 a0 = *(const float4*)&As[kk][ty * 8];
            float4 a1 = *(const float4*)&As[kk][ty * 8 + 4];
            float4 b0 = *(const float4*)&Bs[kk][tx * 8];
            float4 b1 = *(const float4*)&Bs[kk][tx * 8 + 4];
            float av[8] = {a0.x, a0.y, a0.z, a0.w, a1.x, a1.y, a1.z, a1.w};
            float bv[8] = {b0.x, b0.y, b0.z, b0.w, b1.x, b1.y, b1.z, b1.w};
#pragma unroll
            for (int i = 0; i < 8; i++)
#pragma unroll
                for (int j = 0; j < 8; j++)
                    acc[i][j] = fmaf(av[i], bv[j], acc[i][j]);
        }
        __syncthreads();
    }

    // epilogue
    const int gn = gn0 + tx * 8;
    float bb[8];
    *(float4*)&bb[0] = *(const float4*)(bias + (size_t)e * NCOLS + gn);
    *(float4*)&bb[4] = *(const float4*)(bias + (size_t)e * NCOLS + gn + 4);

#pragma unroll
    for (int i = 0; i < 8; i++) {
        int li = ty * 8 + i;
        int p  = s_row[li];
        if (p < 0) continue;
        float4 v0, v1;
        if (MODE == 0) {
            v0.x = fmaxf(acc[i][0] + bb[0], 0.f);
            v0.y = fmaxf(acc[i][1] + bb[1], 0.f);
            v0.z = fmaxf(acc[i][2] + bb[2], 0.f);
            v0.w = fmaxf(acc[i][3] + bb[3], 0.f);
            v1.x = fmaxf(acc[i][4] + bb[4], 0.f);
            v1.y = fmaxf(acc[i][5] + bb[5], 0.f);
            v1.z = fmaxf(acc[i][6] + bb[6], 0.f);
            v1.w = fmaxf(acc[i][7] + bb[7], 0.f);
            float* op = g_h + (size_t)p * HIDDEN + gn;
            *(float4*)op       = v0;
            *(float4*)(op + 4) = v1;
        } else {
            float gw = s_gw[li];
            v0.x = gw * (acc[i][0] + bb[0]);
            v0.y = gw * (acc[i][1] + bb[1]);
            v0.z = gw * (acc[i][2] + bb[2]);
            v0.w = gw * (acc[i][3] + bb[3]);
            v1.x = gw * (acc[i][4] + bb[4]);
            v1.y = gw * (acc[i][5] + bb[5]);
            v1.z = gw * (acc[i][6] + bb[6]);
            v1.w = gw * (acc[i][7] + bb[7]);
            float* op = g_part + (size_t)p * DIM + gn;
            *(float4*)op       = v0;
            *(float4*)(op + 4) = v1;
        }
    }
}

// ---------------- kernel 4: combine the two slots per token ----------------
__global__ void combine_kernel(float* __restrict__ out) {
    int i = blockIdx.x * blockDim.x + threadIdx.x;    // float4 index
    const int total = NTOK * DIM / 4;
    if (i >= total) return;
    int n  = i / (DIM / 4);
    int d4 = i % (DIM / 4);
    const float4 a = *((const float4*)(g_part + (size_t)(2 * n)     * DIM) + d4);
    const float4 b = *((const float4*)(g_part + (size_t)(2 * n + 1) * DIM) + d4);
    float4 r;
    r.x = a.x + b.x; r.y = a.y + b.y; r.z = a.z + b.z; r.w = a.w + b.w;
    ((float4*)out)[i] = r;
}

// ---------------- launch ----------------
extern "C" void kernel_launch(void* const* d_in, const int* in_sizes, int n_in,
                              void* d_out, int out_size) {
    const float* x  = (const float*)d_in[0];
    const float* Wg = (const float*)d_in[1];
    const float* bg = (const float*)d_in[2];
    const float* W1 = (const float*)d_in[3];
    const float* b1 = (const float*)d_in[4];
    const float* W2 = (const float*)d_in[5];
    const float* b2 = (const float*)d_in[6];
    float* out = (float*)d_out;

    zero_cnt_kernel<<<1, 32>>>();
    gate_kernel<<<NTOK / 8, 256>>>(x, Wg, bg);
    expert_ffn_gemm<0, DIM,    HIDDEN><<<dim3(NTOK / BM, HIDDEN / BN, NEXP), NT>>>(x,      W1, b1);
    expert_ffn_gemm<1, HIDDEN, DIM   ><<<dim3(NTOK / BM, DIM    / BN, NEXP), NT>>>(nullptr, W2, b2);
    combine_kernel<<<(NTOK * DIM / 4 + 255) / 256, 256>>>(out);
}

// round 3
// speedup vs baseline: 3.1662x; 3.1662x over previous
#include <cuda_runtime.h>
#include <math.h>
#include <stdint.h>

#define NTOK   4096
#define DIM    1024
#define NEXP   8
#define HIDDEN 4096

#define BM 128
#define BN 128
#define BKF 32
#define NT 256
#define ROWSTR 36          // SMEM row stride in floats (pad: conflict-free + 16B aligned)

// ---------------- scratch (__device__ statics — alloc-free) ----------------
__device__ int   g_cnt[NEXP];
__device__ int   g_list[NEXP][NTOK];
__device__ float g_gw[NEXP][NTOK];
__device__ float g_xt[(size_t)NTOK * DIM];                // tf32-rounded x (16 MiB)
__device__ float g_h[(size_t)NTOK * 2 * HIDDEN];          // 128 MiB (tf32-rounded)
__device__ float g_part[(size_t)NTOK * 2 * DIM];          // 32 MiB
__device__ float g_W1t[(size_t)NEXP * HIDDEN * DIM];      // [e][n][k] tf32-rounded
__device__ float g_W2t[(size_t)NEXP * DIM * HIDDEN];

// ---------------- helpers ----------------
__device__ __forceinline__ uint32_t smem_u32(const void* p) {
    uint32_t a;
    asm("{ .reg .u64 t; cvta.to.shared.u64 t, %1; cvt.u32.u64 %0, t; }" : "=r"(a) : "l"(p));
    return a;
}
__device__ __forceinline__ float cvt_tf32(float x) {
    uint32_t u;
    asm("cvt.rna.tf32.f32 %0, %1;" : "=r"(u) : "f"(x));
    return __uint_as_float(u);
}
__device__ __forceinline__ void cp_async16(uint32_t dst, const void* src) {
    asm volatile("cp.async.cg.shared.global [%0], [%1], 16;" :: "r"(dst), "l"(src));
}
#define CP_COMMIT() asm volatile("cp.async.commit_group;" ::: "memory")
#define CP_WAIT1()  asm volatile("cp.async.wait_group 1;" ::: "memory")

__device__ __forceinline__ void mma_tf32(float* d, const uint32_t* a, const uint32_t* b) {
    asm volatile(
        "mma.sync.aligned.m16n8k8.row.col.f32.tf32.tf32.f32 "
        "{%0,%1,%2,%3}, {%4,%5,%6,%7}, {%8,%9}, {%0,%1,%2,%3};"
        : "+f"(d[0]), "+f"(d[1]), "+f"(d[2]), "+f"(d[3])
        : "r"(a[0]), "r"(a[1]), "r"(a[2]), "r"(a[3]), "r"(b[0]), "r"(b[1]));
}

// ---------------- kernel 0: reset counters ----------------
__global__ void zero_cnt_kernel() {
    if (threadIdx.x < NEXP) g_cnt[threadIdx.x] = 0;
}

// ---------------- kernel 1: gating (1 warp per token) ----------------
__global__ void gate_kernel(const float* __restrict__ x,
                            const float* __restrict__ Wg,
                            const float* __restrict__ bg) {
    int warp = blockIdx.x * (blockDim.x >> 5) + (threadIdx.x >> 5);
    int lane = threadIdx.x & 31;
    if (warp >= NTOK) return;

    const float* xr = x + (size_t)warp * DIM;
    float acc[NEXP];
#pragma unroll
    for (int e = 0; e < NEXP; e++) acc[e] = 0.f;
    for (int d = lane; d < DIM; d += 32) {
        float xv = xr[d];
        const float4* w = reinterpret_cast<const float4*>(Wg + (size_t)d * NEXP);
        float4 w0 = w[0], w1 = w[1];
        acc[0] = fmaf(xv, w0.x, acc[0]); acc[1] = fmaf(xv, w0.y, acc[1]);
        acc[2] = fmaf(xv, w0.z, acc[2]); acc[3] = fmaf(xv, w0.w, acc[3]);
        acc[4] = fmaf(xv, w1.x, acc[4]); acc[5] = fmaf(xv, w1.y, acc[5]);
        acc[6] = fmaf(xv, w1.z, acc[6]); acc[7] = fmaf(xv, w1.w, acc[7]);
    }
#pragma unroll
    for (int off = 16; off > 0; off >>= 1)
#pragma unroll
        for (int e = 0; e < NEXP; e++)
            acc[e] += __shfl_xor_sync(0xffffffffu, acc[e], off);

    if (lane == 0) {
        float lg[NEXP], mx = -1e30f;
#pragma unroll
        for (int e = 0; e < NEXP; e++) { lg[e] = acc[e] + bg[e]; mx = fmaxf(mx, lg[e]); }
        float p[NEXP], s = 0.f;
#pragma unroll
        for (int e = 0; e < NEXP; e++) { p[e] = expf(lg[e] - mx); s += p[e]; }
        float inv = 1.f / s;
        int i0 = 0;
#pragma unroll
        for (int e = 1; e < NEXP; e++) if (p[e] > p[i0]) i0 = e;
        int i1 = (i0 == 0) ? 1 : 0;
#pragma unroll
        for (int e = 0; e < NEXP; e++) if (e != i0 && p[e] > p[i1]) i1 = e;

        int pos0 = atomicAdd(&g_cnt[i0], 1);
        g_list[i0][pos0] = warp * 2 + 0;  g_gw[i0][pos0] = p[i0] * inv;
        int pos1 = atomicAdd(&g_cnt[i1], 1);
        g_list[i1][pos1] = warp * 2 + 1;  g_gw[i1][pos1] = p[i1] * inv;
    }
}

// ---------------- x tf32 pre-round ----------------
__global__ void round_x_kernel(const float* __restrict__ x) {
    int i = blockIdx.x * blockDim.x + threadIdx.x;     // float4 index
    if (i >= NTOK * DIM / 4) return;
    float4 v = ((const float4*)x)[i];
    v.x = cvt_tf32(v.x); v.y = cvt_tf32(v.y); v.z = cvt_tf32(v.z); v.w = cvt_tf32(v.w);
    ((float4*)g_xt)[i] = v;
}

// ------------- weight transpose + tf32 round: in[e][K][N] -> out[e][N][K] -------------
__global__ void transpose_cvt_kernel(const float* __restrict__ in, float* __restrict__ out,
                                     int K, int N) {
    __shared__ float tile[32][33];
    int e = blockIdx.z;
    size_t base = (size_t)e * K * N;
    int n0 = blockIdx.x * 32, k0 = blockIdx.y * 32;
    int c = threadIdx.x & 31, r = threadIdx.x >> 5;
#pragma unroll
    for (int i = 0; i < 4; i++)
        tile[r + i * 8][c] = cvt_tf32(in[base + (size_t)(k0 + r + i * 8) * N + n0 + c]);
    __syncthreads();
#pragma unroll
    for (int i = 0; i < 4; i++)
        out[base + (size_t)(n0 + r + i * 8) * K + k0 + c] = tile[c][r + i * 8];
}

// ---------------- tf32 mma.sync expert GEMM ----------------
// MODE 0: A = gathered g_xt rows, B = W1t, epi: tf32(relu(acc+b1)) -> g_h
// MODE 1: A = gathered g_h rows,  B = W2t, epi: gw*(acc+b2)        -> g_part
template<int MODE, int KDIM, int NCOLS>
__global__ void __launch_bounds__(NT, 2)
moe_mma(const float* __restrict__ Asrc, const float* __restrict__ Wt,
        const float* __restrict__ bias) {
    const int e   = blockIdx.z;
    const int cnt = g_cnt[e];
    const int m0  = blockIdx.x * BM;
    if (m0 >= cnt) return;

    extern __shared__ float smem[];
    int*   s_row = (int*)smem;               // [128]
    float* s_gw  = smem + 128;               // [128]
    // tiles: stage s: A floats at 256 + s*2*128*ROWSTR, B after A
    const int TILE_F  = BM * ROWSTR;         // 4608 floats
    const int STAGE_F = 2 * TILE_F;          // A+B
    float* tiles = smem + 256;

    const int tid  = threadIdx.x;
    const int wid  = tid >> 5, lane = tid & 31;
    const int wm   = (wid >> 2) * 64;        // warp m offset (0,64)
    const int wn   = (wid & 3) * 32;         // warp n offset (0..96)
    const int g    = lane >> 2;              // 0..7
    const int tg   = lane & 3;               // 0..3

    for (int i = tid; i < BM; i += NT) {
        int r = m0 + i;
        if (r < cnt) { s_row[i] = g_list[e][r]; s_gw[i] = g_gw[e][r]; }
        else         { s_row[i] = -1;           s_gw[i] = 0.f; }
    }
    __syncthreads();

    const int gn0 = blockIdx.y * BN;
    const uint32_t smem_base = smem_u32(smem);
    const uint32_t tiles_b   = smem_base + 256 * 4;

    // per-thread cp.async plan: 4 chunks of 16B for A, 4 for B
    const float* a_src[4]; uint32_t a_dst[4];
    const float* b_src[4]; uint32_t b_dst[4];
#pragma unroll
    for (int i = 0; i < 4; i++) {
        int u = tid + i * NT, row = u >> 3, c4 = u & 7;
        int p = s_row[row];
        int arow = (p >= 0) ? (MODE == 0 ? (p >> 1) : p) : 0;   // clamp; discarded in epi
        a_src[i] = Asrc + (size_t)arow * KDIM + c4 * 4;
        a_dst[i] = (uint32_t)(row * ROWSTR * 4 + c4 * 16);
        b_src[i] = Wt + ((size_t)e * NCOLS + gn0 + row) * KDIM + c4 * 4;
        b_dst[i] = (uint32_t)(TILE_F * 4 + row * ROWSTR * 4 + c4 * 16);
    }

    float acc[4][4][4];
#pragma unroll
    for (int i = 0; i < 4; i++)
#pragma unroll
        for (int j = 0; j < 4; j++)
#pragma unroll
            for (int q = 0; q < 4; q++) acc[i][j][q] = 0.f;

    const int KT = KDIM / BKF;

    // prologue: stage 0
#pragma unroll
    for (int i = 0; i < 4; i++) {
        cp_async16(tiles_b + a_dst[i], a_src[i]);
        cp_async16(tiles_b + b_dst[i], b_src[i]);
    }
    CP_COMMIT();

#pragma unroll 1
    for (int t = 0; t < KT; ++t) {
        if (t + 1 < KT) {
            const uint32_t sb = tiles_b + ((t + 1) & 1) * STAGE_F * 4;
            const int k1 = (t + 1) * BKF;
#pragma unroll
            for (int i = 0; i < 4; i++) {
                cp_async16(sb + a_dst[i], a_src[i] + k1);
                cp_async16(sb + b_dst[i], b_src[i] + k1);
            }
        }
        CP_COMMIT();
        CP_WAIT1();
        __syncthreads();

        const float* As = tiles + (t & 1) * STAGE_F;
        const float* Bs = As + TILE_F;
#pragma unroll
        for (int s = 0; s < 4; s++) {
            const int k8 = s * 8;
            uint32_t af[4][4];
#pragma unroll
            for (int i = 0; i < 4; i++) {
                const float* ar = As + (wm + i * 16 + g) * ROWSTR + k8;
                af[i][0] = __float_as_uint(ar[tg]);
                af[i][1] = __float_as_uint(ar[8 * ROWSTR + tg]);
                af[i][2] = __float_as_uint(ar[tg + 4]);
                af[i][3] = __float_as_uint(ar[8 * ROWSTR + tg + 4]);
            }
            uint32_t bf[4][2];
#pragma unroll
            for (int j = 0; j < 4; j++) {
                const float* br = Bs + (wn + j * 8 + g) * ROWSTR + k8;
                bf[j][0] = __float_as_uint(br[tg]);
                bf[j][1] = __float_as_uint(br[tg + 4]);
            }
#pragma unroll
            for (int i = 0; i < 4; i++)
#pragma unroll
                for (int j = 0; j < 4; j++)
                    mma_tf32(acc[i][j], af[i], bf[j]);
        }
        __syncthreads();
    }

    // ---------------- epilogue ----------------
#pragma unroll
    for (int i = 0; i < 4; i++) {
        const int rl = wm + i * 16 + g;       // local m rows rl, rl+8
        const int pl = s_row[rl],  ph = s_row[rl + 8];
        const float gl = s_gw[rl], gh = s_gw[rl + 8];
#pragma unroll
        for (int j = 0; j < 4; j++) {
            const int n = gn0 + wn + j * 8 + 2 * tg;
            const float2 bb = *(const float2*)(bias + (size_t)e * NCOLS + n);
            if (MODE == 0) {
                if (pl >= 0) {
                    float2 v;
                    v.x = cvt_tf32(fmaxf(acc[i][j][0] + bb.x, 0.f));
                    v.y = cvt_tf32(fmaxf(acc[i][j][1] + bb.y, 0.f));
                    *(float2*)(g_h + (size_t)pl * HIDDEN + n) = v;
                }
                if (ph >= 0) {
                    float2 v;
                    v.x = cvt_tf32(fmaxf(acc[i][j][2] + bb.x, 0.f));
                    v.y = cvt_tf32(fmaxf(acc[i][j][3] + bb.y, 0.f));
                    *(float2*)(g_h + (size_t)ph * HIDDEN + n) = v;
                }
            } else {
                if (pl >= 0) {
                    float2 v;
                    v.x = gl * (acc[i][j][0] + bb.x);
                    v.y = gl * (acc[i][j][1] + bb.y);
                    *(float2*)(g_part + (size_t)pl * DIM + n) = v;
                }
                if (ph >= 0) {
                    float2 v;
                    v.x = gh * (acc[i][j][2] + bb.x);
                    v.y = gh * (acc[i][j][3] + bb.y);
                    *(float2*)(g_part + (size_t)ph * DIM + n) = v;
                }
            }
        }
    }
}

// ---------------- kernel: combine the two slots per token ----------------
__global__ void combine_kernel(float* __restrict__ out) {
    int i = blockIdx.x * blockDim.x + threadIdx.x;
    const int total = NTOK * DIM / 4;
    if (i >= total) return;
    int n = i / (DIM / 4), d4 = i % (DIM / 4);
    const float4 a = *((const float4*)(g_part + (size_t)(2 * n)     * DIM) + d4);
    const float4 b = *((const float4*)(g_part + (size_t)(2 * n + 1) * DIM) + d4);
    float4 r; r.x = a.x + b.x; r.y = a.y + b.y; r.z = a.z + b.z; r.w = a.w + b.w;
    ((float4*)out)[i] = r;
}

// ---------------- launch ----------------
static constexpr int SMEM_BYTES = (256 + 2 * 2 * BM * ROWSTR) * 4;   // 74752

extern "C" void kernel_launch(void* const* d_in, const int* in_sizes, int n_in,
                              void* d_out, int out_size) {
    const float* x  = (const float*)d_in[0];
    const float* Wg = (const float*)d_in[1];
    const float* bg = (const float*)d_in[2];
    const float* W1 = (const float*)d_in[3];
    const float* b1 = (const float*)d_in[4];
    const float* W2 = (const float*)d_in[5];
    const float* b2 = (const float*)d_in[6];
    float* out = (float*)d_out;

    cudaFuncSetAttribute(moe_mma<0, DIM, HIDDEN>,
                         cudaFuncAttributeMaxDynamicSharedMemorySize, SMEM_BYTES);
    cudaFuncSetAttribute(moe_mma<1, HIDDEN, DIM>,
                         cudaFuncAttributeMaxDynamicSharedMemorySize, SMEM_BYTES);

    float* W1t; cudaGetSymbolAddress((void**)&W1t, g_W1t);
    float* W2t; cudaGetSymbolAddress((void**)&W2t, g_W2t);
    float* xt;  cudaGetSymbolAddress((void**)&xt,  g_xt);
    float* gh;  cudaGetSymbolAddress((void**)&gh,  g_h);

    zero_cnt_kernel<<<1, 32>>>();
    gate_kernel<<<NTOK / 8, 256>>>(x, Wg, bg);
    round_x_kernel<<<(NTOK * DIM / 4 + 255) / 256, 256>>>(x);
    transpose_cvt_kernel<<<dim3(HIDDEN / 32, DIM / 32, NEXP), 256>>>(W1, W1t, DIM, HIDDEN);
    transpose_cvt_kernel<<<dim3(DIM / 32, HIDDEN / 32, NEXP), 256>>>(W2, W2t, HIDDEN, DIM);
    moe_mma<0, DIM, HIDDEN><<<dim3(NTOK / BM, HIDDEN / BN, NEXP), NT, SMEM_BYTES>>>(xt, W1t, b1);
    moe_mma<1, HIDDEN, DIM><<<dim3(NTOK / BM, DIM / BN, NEXP), NT, SMEM_BYTES>>>(gh, W2t, b2);
    combine_kernel<<<(NTOK * DIM / 4 + 255) / 256, 256>>>(out);
}

// round 4
// speedup vs baseline: 3.2869x; 1.0381x over previous
#include <cuda_runtime.h>
#include <math.h>
#include <stdint.h>

#define NTOK   4096
#define DIM    1024
#define NEXP   8
#define HIDDEN 4096

#define BM 128
#define BN 128
#define BKF 32
#define NT 128
#define ROWSTR 36          // SMEM row stride in floats (conflict-free + 16B aligned)

// ---------------- scratch (__device__ statics — alloc-free) ----------------
__device__ int   g_cnt[NEXP];
__device__ int   g_list[NEXP][NTOK];
__device__ float g_gw[NEXP][NTOK];
__device__ float g_xt[(size_t)NTOK * DIM];                // tf32-rounded x
__device__ float g_h[(size_t)NTOK * 2 * HIDDEN];          // tf32-rounded hidden
__device__ float g_part[(size_t)NTOK * 2 * DIM];
__device__ float g_W1t[(size_t)NEXP * HIDDEN * DIM];      // [e][n][k] tf32-rounded
__device__ float g_W2t[(size_t)NEXP * DIM * HIDDEN];

// ---------------- helpers ----------------
__device__ __forceinline__ float cvt_tf32(float x) {
    uint32_t u;
    asm("cvt.rna.tf32.f32 %0, %1;" : "=r"(u) : "f"(x));
    return __uint_as_float(u);
}
__device__ __forceinline__ uint32_t smem_u32(const void* p) {
    uint32_t a;
    asm("{ .reg .u64 t; cvta.to.shared.u64 t, %1; cvt.u32.u64 %0, t; }" : "=r"(a) : "l"(p));
    return a;
}
__device__ __forceinline__ void cp_async16(uint32_t dst, const void* src) {
    asm volatile("cp.async.cg.shared.global [%0], [%1], 16;" :: "r"(dst), "l"(src));
}
#define CP_COMMIT() asm volatile("cp.async.commit_group;" ::: "memory")
#define CP_WAIT1()  asm volatile("cp.async.wait_group 1;" ::: "memory")

__device__ __forceinline__ void mma_tf32(float* d, const uint32_t* a, const uint32_t* b) {
    asm volatile(
        "mma.sync.aligned.m16n8k8.row.col.f32.tf32.tf32.f32 "
        "{%0,%1,%2,%3}, {%4,%5,%6,%7}, {%8,%9}, {%0,%1,%2,%3};"
        : "+f"(d[0]), "+f"(d[1]), "+f"(d[2]), "+f"(d[3])
        : "r"(a[0]), "r"(a[1]), "r"(a[2]), "r"(a[3]), "r"(b[0]), "r"(b[1]));
}

// ---------------- kernel 0: reset counters ----------------
__global__ void zero_cnt_kernel() {
    if (threadIdx.x < NEXP) g_cnt[threadIdx.x] = 0;
}

// ---------------- kernel 1: gating (1 warp per token) ----------------
__global__ void gate_kernel(const float* __restrict__ x,
                            const float* __restrict__ Wg,
                            const float* __restrict__ bg) {
    int warp = blockIdx.x * (blockDim.x >> 5) + (threadIdx.x >> 5);
    int lane = threadIdx.x & 31;
    if (warp >= NTOK) return;

    const float* xr = x + (size_t)warp * DIM;
    float acc[NEXP];
#pragma unroll
    for (int e = 0; e < NEXP; e++) acc[e] = 0.f;
    for (int d = lane; d < DIM; d += 32) {
        float xv = xr[d];
        const float4* w = reinterpret_cast<const float4*>(Wg + (size_t)d * NEXP);
        float4 w0 = w[0], w1 = w[1];
        acc[0] = fmaf(xv, w0.x, acc[0]); acc[1] = fmaf(xv, w0.y, acc[1]);
        acc[2] = fmaf(xv, w0.z, acc[2]); acc[3] = fmaf(xv, w0.w, acc[3]);
        acc[4] = fmaf(xv, w1.x, acc[4]); acc[5] = fmaf(xv, w1.y, acc[5]);
        acc[6] = fmaf(xv, w1.z, acc[6]); acc[7] = fmaf(xv, w1.w, acc[7]);
    }
#pragma unroll
    for (int off = 16; off > 0; off >>= 1)
#pragma unroll
        for (int e = 0; e < NEXP; e++)
            acc[e] += __shfl_xor_sync(0xffffffffu, acc[e], off);

    if (lane == 0) {
        float lg[NEXP], mx = -1e30f;
#pragma unroll
        for (int e = 0; e < NEXP; e++) { lg[e] = acc[e] + bg[e]; mx = fmaxf(mx, lg[e]); }
        float p[NEXP], s = 0.f;
#pragma unroll
        for (int e = 0; e < NEXP; e++) { p[e] = expf(lg[e] - mx); s += p[e]; }
        float inv = 1.f / s;
        int i0 = 0;
#pragma unroll
        for (int e = 1; e < NEXP; e++) if (p[e] > p[i0]) i0 = e;
        int i1 = (i0 == 0) ? 1 : 0;
#pragma unroll
        for (int e = 0; e < NEXP; e++) if (e != i0 && p[e] > p[i1]) i1 = e;

        int pos0 = atomicAdd(&g_cnt[i0], 1);
        g_list[i0][pos0] = warp * 2 + 0;  g_gw[i0][pos0] = p[i0] * inv;
        int pos1 = atomicAdd(&g_cnt[i1], 1);
        g_list[i1][pos1] = warp * 2 + 1;  g_gw[i1][pos1] = p[i1] * inv;
    }
}

// ---------------- x tf32 pre-round ----------------
__global__ void round_x_kernel(const float* __restrict__ x) {
    int i = blockIdx.x * blockDim.x + threadIdx.x;
    if (i >= NTOK * DIM / 4) return;
    float4 v = ((const float4*)x)[i];
    v.x = cvt_tf32(v.x); v.y = cvt_tf32(v.y); v.z = cvt_tf32(v.z); v.w = cvt_tf32(v.w);
    ((float4*)g_xt)[i] = v;
}

// ------------- weight transpose + tf32 round: in[e][K][N] -> out[e][N][K] -------------
__global__ void transpose_cvt_kernel(const float* __restrict__ in, float* __restrict__ out,
                                     int K, int N) {
    __shared__ float tile[32][33];
    int e = blockIdx.z;
    size_t base = (size_t)e * K * N;
    int n0 = blockIdx.x * 32, k0 = blockIdx.y * 32;
    int c = threadIdx.x & 31, r = threadIdx.x >> 5;
#pragma unroll
    for (int i = 0; i < 4; i++)
        tile[r + i * 8][c] = cvt_tf32(in[base + (size_t)(k0 + r + i * 8) * N + n0 + c]);
    __syncthreads();
#pragma unroll
    for (int i = 0; i < 4; i++)
        out[base + (size_t)(n0 + r + i * 8) * K + k0 + c] = tile[c][r + i * 8];
}

// ---------------- tf32 mma.sync expert GEMM (4 warps, 64x64 warp tile) ----------------
// MODE 0: A = gathered g_xt rows, B = W1t, epi: tf32(relu(acc+b1)) -> g_h
// MODE 1: A = gathered g_h rows,  B = W2t, epi: gw*(acc+b2)        -> g_part
template<int MODE, int KDIM, int NCOLS>
__global__ void __launch_bounds__(NT, 2)
moe_mma(const float* __restrict__ Asrc, const float* __restrict__ Wt,
        const float* __restrict__ bias) {
    const int e   = blockIdx.z;
    const int cnt = g_cnt[e];
    const int m0  = blockIdx.x * BM;
    if (m0 >= cnt) return;

    extern __shared__ float smem[];
    int*   s_row = (int*)smem;               // [128]
    float* s_gw  = smem + 128;               // [128]
    const int TILE_F  = BM * ROWSTR;         // 4608 floats
    const int STAGE_F = 2 * TILE_F;
    float* tiles = smem + 256;

    const int tid  = threadIdx.x;
    const int wid  = tid >> 5, lane = tid & 31;
    const int wm   = (wid >> 1) * 64;        // 0,64
    const int wn   = (wid & 1) * 64;         // 0,64
    const int g    = lane >> 2;              // 0..7
    const int tg   = lane & 3;               // 0..3

    for (int i = tid; i < BM; i += NT) {
        int r = m0 + i;
        if (r < cnt) { s_row[i] = g_list[e][r]; s_gw[i] = g_gw[e][r]; }
        else         { s_row[i] = -1;           s_gw[i] = 0.f; }
    }
    __syncthreads();

    const int gn0 = blockIdx.y * BN;
    const uint32_t tiles_b = smem_u32(smem) + 256 * 4;

    // cp.async plan: 8 A chunks + 8 B chunks of 16B per thread
    // chunk i covers row = (tid>>3) + i*16, c4 = tid&7
    const int lrow = tid >> 3, c4 = tid & 7;
    uint32_t a_off[8];                         // element offsets into Asrc
#pragma unroll
    for (int i = 0; i < 8; i++) {
        int p = s_row[lrow + i * 16];
        int arow = (p >= 0) ? (MODE == 0 ? (p >> 1) : p) : 0;
        a_off[i] = (uint32_t)arow * KDIM + c4 * 4;
    }
    const float* b_base = Wt + ((size_t)e * NCOLS + gn0 + lrow) * KDIM + c4 * 4;
    const uint32_t a_dst0 = (uint32_t)(lrow * ROWSTR * 4 + c4 * 16);
    const uint32_t b_dst0 = (uint32_t)(TILE_F * 4 + lrow * ROWSTR * 4 + c4 * 16);
    const uint32_t rstep  = 16 * ROWSTR * 4;   // 16 rows in smem bytes

    float acc[4][8][4];
#pragma unroll
    for (int i = 0; i < 4; i++)
#pragma unroll
        for (int j = 0; j < 8; j++)
#pragma unroll
            for (int q = 0; q < 4; q++) acc[i][j][q] = 0.f;

    const int KT = KDIM / BKF;

    // prologue: stage 0
#pragma unroll
    for (int i = 0; i < 8; i++) {
        cp_async16(tiles_b + a_dst0 + i * rstep, Asrc + a_off[i]);
        cp_async16(tiles_b + b_dst0 + i * rstep, b_base + (size_t)i * 16 * KDIM);
    }
    CP_COMMIT();

#pragma unroll 1
    for (int t = 0; t < KT; ++t) {
        if (t + 1 < KT) {
            const uint32_t sb = tiles_b + ((t + 1) & 1) * STAGE_F * 4;
            const int k1 = (t + 1) * BKF;
#pragma unroll
            for (int i = 0; i < 8; i++) {
                cp_async16(sb + a_dst0 + i * rstep, Asrc + a_off[i] + k1);
                cp_async16(sb + b_dst0 + i * rstep, b_base + (size_t)i * 16 * KDIM + k1);
            }
        }
        CP_COMMIT();
        CP_WAIT1();
        __syncthreads();

        const float* As = tiles + (t & 1) * STAGE_F;
        const float* Bs = As + TILE_F;
#pragma unroll
        for (int s = 0; s < 4; s++) {
            const int k8 = s * 8;
            uint32_t af[4][4];
#pragma unroll
            for (int i = 0; i < 4; i++) {
                const float* ar = As + (wm + i * 16 + g) * ROWSTR + k8;
                af[i][0] = __float_as_uint(ar[tg]);
                af[i][1] = __float_as_uint(ar[8 * ROWSTR + tg]);
                af[i][2] = __float_as_uint(ar[tg + 4]);
                af[i][3] = __float_as_uint(ar[8 * ROWSTR + tg + 4]);
            }
            uint32_t bf[8][2];
#pragma unroll
            for (int j = 0; j < 8; j++) {
                const float* br = Bs + (wn + j * 8 + g) * ROWSTR + k8;
                bf[j][0] = __float_as_uint(br[tg]);
                bf[j][1] = __float_as_uint(br[tg + 4]);
            }
#pragma unroll
            for (int i = 0; i < 4; i++)
#pragma unroll
                for (int j = 0; j < 8; j++)
                    mma_tf32(acc[i][j], af[i], bf[j]);
        }
        __syncthreads();
    }

    // ---------------- epilogue ----------------
#pragma unroll
    for (int i = 0; i < 4; i++) {
        const int rl = wm + i * 16 + g;
        const int pl = s_row[rl],  ph = s_row[rl + 8];
        const float gl = s_gw[rl], gh = s_gw[rl + 8];
#pragma unroll
        for (int j = 0; j < 8; j++) {
            const int n = gn0 + wn + j * 8 + 2 * tg;
            const float2 bb = *(const float2*)(bias + (size_t)e * NCOLS + n);
            if (MODE == 0) {
                if (pl >= 0) {
                    float2 v;
                    v.x = cvt_tf32(fmaxf(acc[i][j][0] + bb.x, 0.f));
                    v.y = cvt_tf32(fmaxf(acc[i][j][1] + bb.y, 0.f));
                    *(float2*)(g_h + (size_t)pl * HIDDEN + n) = v;
                }
                if (ph >= 0) {
                    float2 v;
                    v.x = cvt_tf32(fmaxf(acc[i][j][2] + bb.x, 0.f));
                    v.y = cvt_tf32(fmaxf(acc[i][j][3] + bb.y, 0.f));
                    *(float2*)(g_h + (size_t)ph * HIDDEN + n) = v;
                }
            } else {
                if (pl >= 0) {
                    float2 v;
                    v.x = gl * (acc[i][j][0] + bb.x);
                    v.y = gl * (acc[i][j][1] + bb.y);
                    *(float2*)(g_part + (size_t)pl * DIM + n) = v;
                }
                if (ph >= 0) {
                    float2 v;
                    v.x = gh * (acc[i][j][2] + bb.x);
                    v.y = gh * (acc[i][j][3] + bb.y);
                    *(float2*)(g_part + (size_t)ph * DIM + n) = v;
                }
            }
        }
    }
}

// ---------------- kernel: combine the two slots per token ----------------
__global__ void combine_kernel(float* __restrict__ out) {
    int i = blockIdx.x * blockDim.x + threadIdx.x;
    const int total = NTOK * DIM / 4;
    if (i >= total) return;
    int n = i / (DIM / 4), d4 = i % (DIM / 4);
    const float4 a = *((const float4*)(g_part + (size_t)(2 * n)     * DIM) + d4);
    const float4 b = *((const float4*)(g_part + (size_t)(2 * n + 1) * DIM) + d4);
    float4 r; r.x = a.x + b.x; r.y = a.y + b.y; r.z = a.z + b.z; r.w = a.w + b.w;
    ((float4*)out)[i] = r;
}

// ---------------- launch ----------------
static constexpr int SMEM_BYTES = (256 + 2 * 2 * BM * ROWSTR) * 4;   // 74752

extern "C" void kernel_launch(void* const* d_in, const int* in_sizes, int n_in,
                              void* d_out, int out_size) {
    const float* x  = (const float*)d_in[0];
    const float* Wg = (const float*)d_in[1];
    const float* bg = (const float*)d_in[2];
    const float* W1 = (const float*)d_in[3];
    const float* b1 = (const float*)d_in[4];
    const float* W2 = (const float*)d_in[5];
    const float* b2 = (const float*)d_in[6];
    float* out = (float*)d_out;

    cudaFuncSetAttribute(moe_mma<0, DIM, HIDDEN>,
                         cudaFuncAttributeMaxDynamicSharedMemorySize, SMEM_BYTES);
    cudaFuncSetAttribute(moe_mma<1, HIDDEN, DIM>,
                         cudaFuncAttributeMaxDynamicSharedMemorySize, SMEM_BYTES);

    float* W1t; cudaGetSymbolAddress((void**)&W1t, g_W1t);
    float* W2t; cudaGetSymbolAddress((void**)&W2t, g_W2t);
    float* xt;  cudaGetSymbolAddress((void**)&xt,  g_xt);
    float* gh;  cudaGetSymbolAddress((void**)&gh,  g_h);

    zero_cnt_kernel<<<1, 32>>>();
    gate_kernel<<<NTOK / 8, 256>>>(x, Wg, bg);
    round_x_kernel<<<(NTOK * DIM / 4 + 255) / 256, 256>>>(x);
    transpose_cvt_kernel<<<dim3(HIDDEN / 32, DIM / 32, NEXP), 256>>>(W1, W1t, DIM, HIDDEN);
    transpose_cvt_kernel<<<dim3(DIM / 32, HIDDEN / 32, NEXP), 256>>>(W2, W2t, HIDDEN, DIM);
    moe_mma<0, DIM, HIDDEN><<<dim3(NTOK / BM, HIDDEN / BN, NEXP), NT, SMEM_BYTES>>>(xt, W1t, b1);
    moe_mma<1, HIDDEN, DIM><<<dim3(NTOK / BM, DIM / BN, NEXP), NT, SMEM_BYTES>>>(gh, W2t, b2);
    combine_kernel<<<(NTOK * DIM / 4 + 255) / 256, 256>>>(out);
}

// round 5
// speedup vs baseline: 5.8225x; 1.7714x over previous
#include <cuda_runtime.h>
#include <cuda_fp16.h>
#include <math.h>
#include <stdint.h>

#define NTOK   4096
#define DIM    1024
#define NEXP   8
#define HIDDEN 4096

#define BM 128
#define BN 128
#define BKH 64            // K halfs per SMEM k-tile (128 B of payload per row)
#define NT 128
#define ROWB 144          // SMEM row stride in bytes (128 payload + 16 pad, LDSM conflict-free)

// ---------------- scratch (__device__ statics — alloc-free) ----------------
__device__ int    g_cnt[NEXP];
__device__ int    g_list[NEXP][NTOK];
__device__ float  g_gw[NEXP][NTOK];
__device__ __half g_xh[(size_t)NTOK * DIM];               // fp16 x (8 MiB)
__device__ __half g_h[(size_t)NTOK * 2 * HIDDEN];         // fp16 hidden (64 MiB)
__device__ float  g_part[(size_t)NTOK * 2 * DIM];         // 32 MiB
__device__ __half g_W1t[(size_t)NEXP * HIDDEN * DIM];     // [e][n][k] fp16 (64 MiB)
__device__ __half g_W2t[(size_t)NEXP * DIM * HIDDEN];     // (64 MiB)

// ---------------- helpers ----------------
__device__ __forceinline__ uint32_t smem_u32(const void* p) {
    uint32_t a;
    asm("{ .reg .u64 t; cvta.to.shared.u64 t, %1; cvt.u32.u64 %0, t; }" : "=r"(a) : "l"(p));
    return a;
}
__device__ __forceinline__ void cp_async16(uint32_t dst, const void* src) {
    asm volatile("cp.async.cg.shared.global [%0], [%1], 16;" :: "r"(dst), "l"(src));
}
#define CP_COMMIT() asm volatile("cp.async.commit_group;" ::: "memory")
#define CP_WAIT1()  asm volatile("cp.async.wait_group 1;" ::: "memory")

__device__ __forceinline__ void ldsm_x4(uint32_t* r, uint32_t addr) {
    asm volatile("ldmatrix.sync.aligned.m8n8.x4.shared.b16 {%0,%1,%2,%3}, [%4];"
                 : "=r"(r[0]), "=r"(r[1]), "=r"(r[2]), "=r"(r[3]) : "r"(addr));
}
__device__ __forceinline__ void mma_f16(float* d, const uint32_t* a, uint32_t b0, uint32_t b1) {
    asm volatile(
        "mma.sync.aligned.m16n8k16.row.col.f32.f16.f16.f32 "
        "{%0,%1,%2,%3}, {%4,%5,%6,%7}, {%8,%9}, {%0,%1,%2,%3};"
        : "+f"(d[0]), "+f"(d[1]), "+f"(d[2]), "+f"(d[3])
        : "r"(a[0]), "r"(a[1]), "r"(a[2]), "r"(a[3]), "r"(b0), "r"(b1));
}

// ---------------- kernel 0: reset counters ----------------
__global__ void zero_cnt_kernel() {
    if (threadIdx.x < NEXP) g_cnt[threadIdx.x] = 0;
}

// ---------------- kernel 1: gating (1 warp per token) ----------------
__global__ void gate_kernel(const float* __restrict__ x,
                            const float* __restrict__ Wg,
                            const float* __restrict__ bg) {
    int warp = blockIdx.x * (blockDim.x >> 5) + (threadIdx.x >> 5);
    int lane = threadIdx.x & 31;
    if (warp >= NTOK) return;

    const float* xr = x + (size_t)warp * DIM;
    float acc[NEXP];
#pragma unroll
    for (int e = 0; e < NEXP; e++) acc[e] = 0.f;
    for (int d = lane; d < DIM; d += 32) {
        float xv = xr[d];
        const float4* w = reinterpret_cast<const float4*>(Wg + (size_t)d * NEXP);
        float4 w0 = w[0], w1 = w[1];
        acc[0] = fmaf(xv, w0.x, acc[0]); acc[1] = fmaf(xv, w0.y, acc[1]);
        acc[2] = fmaf(xv, w0.z, acc[2]); acc[3] = fmaf(xv, w0.w, acc[3]);
        acc[4] = fmaf(xv, w1.x, acc[4]); acc[5] = fmaf(xv, w1.y, acc[5]);
        acc[6] = fmaf(xv, w1.z, acc[6]); acc[7] = fmaf(xv, w1.w, acc[7]);
    }
#pragma unroll
    for (int off = 16; off > 0; off >>= 1)
#pragma unroll
        for (int e = 0; e < NEXP; e++)
            acc[e] += __shfl_xor_sync(0xffffffffu, acc[e], off);

    if (lane == 0) {
        float lg[NEXP], mx = -1e30f;
#pragma unroll
        for (int e = 0; e < NEXP; e++) { lg[e] = acc[e] + bg[e]; mx = fmaxf(mx, lg[e]); }
        float p[NEXP], s = 0.f;
#pragma unroll
        for (int e = 0; e < NEXP; e++) { p[e] = expf(lg[e] - mx); s += p[e]; }
        float inv = 1.f / s;
        int i0 = 0;
#pragma unroll
        for (int e = 1; e < NEXP; e++) if (p[e] > p[i0]) i0 = e;
        int i1 = (i0 == 0) ? 1 : 0;
#pragma unroll
        for (int e = 0; e < NEXP; e++) if (e != i0 && p[e] > p[i1]) i1 = e;

        int pos0 = atomicAdd(&g_cnt[i0], 1);
        g_list[i0][pos0] = warp * 2 + 0;  g_gw[i0][pos0] = p[i0] * inv;
        int pos1 = atomicAdd(&g_cnt[i1], 1);
        g_list[i1][pos1] = warp * 2 + 1;  g_gw[i1][pos1] = p[i1] * inv;
    }
}

// ---------------- x fp16 pre-round ----------------
__global__ void round_x_kernel(const float* __restrict__ x) {
    int i = blockIdx.x * blockDim.x + threadIdx.x;       // 4-float unit
    if (i >= NTOK * DIM / 4) return;
    float4 v = ((const float4*)x)[i];
    __half2* o = (__half2*)(g_xh + (size_t)i * 4);
    o[0] = __floats2half2_rn(v.x, v.y);
    o[1] = __floats2half2_rn(v.z, v.w);
}

// ------------- weight transpose + fp16 cvt: in fp32 [e][K][N] -> out half [e][N][K] ----
__global__ void transpose_cvt_kernel(const float* __restrict__ in, __half* __restrict__ out,
                                     int K, int N) {
    __shared__ float tile[32][33];
    int e = blockIdx.z;
    size_t base = (size_t)e * K * N;
    int n0 = blockIdx.x * 32, k0 = blockIdx.y * 32;
    int c = threadIdx.x & 31, r = threadIdx.x >> 5;
#pragma unroll
    for (int i = 0; i < 4; i++)
        tile[r + i * 8][c] = in[base + (size_t)(k0 + r + i * 8) * N + n0 + c];
    __syncthreads();
#pragma unroll
    for (int i = 0; i < 4; i++)
        out[base + (size_t)(n0 + r + i * 8) * K + k0 + c] = __float2half_rn(tile[c][r + i * 8]);
}

// ---------------- fp16 mma.sync expert GEMM (4 warps, 64x64 warp tile) ----------------
// MODE 0: A = gathered g_xh rows, B = W1t, epi: half(relu(acc+b1)) -> g_h
// MODE 1: A = gathered g_h rows,  B = W2t, epi: gw*(acc+b2)        -> g_part
template<int MODE, int KDIM, int NCOLS>
__global__ void __launch_bounds__(NT, 2)
moe_mma(const __half* __restrict__ Asrc, const __half* __restrict__ Wt,
        const float* __restrict__ bias) {
    const int e   = blockIdx.z;
    const int cnt = g_cnt[e];
    const int m0  = blockIdx.x * BM;
    if (m0 >= cnt) return;

    extern __shared__ char smem[];
    int*   s_row = (int*)smem;                 // [128]
    float* s_gw  = (float*)(smem + 512);       // [128]
    const int TILE_B  = BM * ROWB;             // 18432 B
    const int STAGE_B = 2 * TILE_B;            // A+B

    const int tid  = threadIdx.x;
    const int wid  = tid >> 5, lane = tid & 31;
    const int wm   = (wid >> 1) * 64;          // 0,64
    const int wn   = (wid & 1) * 64;           // 0,64
    const int g    = lane >> 2;                // 0..7
    const int tg   = lane & 3;                 // 0..3

    for (int i = tid; i < BM; i += NT) {
        int r = m0 + i;
        if (r < cnt) { s_row[i] = g_list[e][r]; s_gw[i] = g_gw[e][r]; }
        else         { s_row[i] = -1;           s_gw[i] = 0.f; }
    }
    __syncthreads();

    const int gn0 = blockIdx.y * BN;
    const uint32_t tiles_b = smem_u32(smem) + 1024;

    // cp.async plan: 8 A + 8 B 16B chunks per thread; chunk i: row = lrow+16i, col c8
    const int lrow = tid >> 3, c8 = tid & 7;   // 16B = 8 halfs
    uint32_t a_off[8];                          // half-element offsets into Asrc
#pragma unroll
    for (int i = 0; i < 8; i++) {
        int p = s_row[lrow + i * 16];
        int arow = (p >= 0) ? (MODE == 0 ? (p >> 1) : p) : 0;
        a_off[i] = (uint32_t)arow * KDIM + c8 * 8;
    }
    const __half* b_base = Wt + ((size_t)e * NCOLS + gn0 + lrow) * KDIM + c8 * 8;
    const uint32_t a_dst0 = (uint32_t)(lrow * ROWB + c8 * 16);
    const uint32_t b_dst0 = (uint32_t)(TILE_B + lrow * ROWB + c8 * 16);
    const uint32_t rstep  = 16 * ROWB;

    // LDSM per-lane address components
    const uint32_t a_lane = (uint32_t)((lane & 15) * ROWB + (lane >> 4) * 16);
    const int nloc  = (lane & 7) + ((lane >> 4) << 3);
    const uint32_t b_lane = (uint32_t)(nloc * ROWB + ((lane >> 3) & 1) * 16);

    float acc[4][8][4];
#pragma unroll
    for (int i = 0; i < 4; i++)
#pragma unroll
        for (int j = 0; j < 8; j++)
#pragma unroll
            for (int q = 0; q < 4; q++) acc[i][j][q] = 0.f;

    const int KT = KDIM / BKH;

    // prologue: stage 0
#pragma unroll
    for (int i = 0; i < 8; i++) {
        cp_async16(tiles_b + a_dst0 + i * rstep, Asrc + a_off[i]);
        cp_async16(tiles_b + b_dst0 + i * rstep, b_base + (size_t)i * 16 * KDIM);
    }
    CP_COMMIT();

#pragma unroll 1
    for (int t = 0; t < KT; ++t) {
        if (t + 1 < KT) {
            const uint32_t sb = tiles_b + ((t + 1) & 1) * STAGE_B;
            const int k1 = (t + 1) * BKH;
#pragma unroll
            for (int i = 0; i < 8; i++) {
                cp_async16(sb + a_dst0 + i * rstep, Asrc + a_off[i] + k1);
                cp_async16(sb + b_dst0 + i * rstep, b_base + (size_t)i * 16 * KDIM + k1);
            }
        }
        CP_COMMIT();
        CP_WAIT1();
        __syncthreads();

        const uint32_t As_b = tiles_b + (t & 1) * STAGE_B;
        const uint32_t Bs_b = As_b + TILE_B;
#pragma unroll
        for (int s = 0; s < 4; s++) {
            const uint32_t kb = s * 32;        // 16 halfs = 32 B per k16 step
            uint32_t af[4][4];
#pragma unroll
            for (int i = 0; i < 4; i++)
                ldsm_x4(af[i], As_b + (uint32_t)(wm + 16 * i) * ROWB + kb + a_lane);
            uint32_t bf[4][4];
#pragma unroll
            for (int j2 = 0; j2 < 4; j2++)
                ldsm_x4(bf[j2], Bs_b + (uint32_t)(wn + 16 * j2) * ROWB + kb + b_lane);
#pragma unroll
            for (int i = 0; i < 4; i++)
#pragma unroll
                for (int j2 = 0; j2 < 4; j2++) {
                    mma_f16(acc[i][2 * j2],     af[i], bf[j2][0], bf[j2][1]);
                    mma_f16(acc[i][2 * j2 + 1], af[i], bf[j2][2], bf[j2][3]);
                }
        }
        __syncthreads();
    }

    // ---------------- epilogue ----------------
#pragma unroll
    for (int i = 0; i < 4; i++) {
        const int rl = wm + i * 16 + g;
        const int pl = s_row[rl],  ph = s_row[rl + 8];
        const float gl = s_gw[rl], gh2 = s_gw[rl + 8];
#pragma unroll
        for (int j = 0; j < 8; j++) {
            const int n = gn0 + wn + j * 8 + 2 * tg;
            const float2 bb = *(const float2*)(bias + (size_t)e * NCOLS + n);
            if (MODE == 0) {
                if (pl >= 0)
                    *(__half2*)(g_h + (size_t)pl * HIDDEN + n) =
                        __floats2half2_rn(fmaxf(acc[i][j][0] + bb.x, 0.f),
                                          fmaxf(acc[i][j][1] + bb.y, 0.f));
                if (ph >= 0)
                    *(__half2*)(g_h + (size_t)ph * HIDDEN + n) =
                        __floats2half2_rn(fmaxf(acc[i][j][2] + bb.x, 0.f),
                                          fmaxf(acc[i][j][3] + bb.y, 0.f));
            } else {
                if (pl >= 0) {
                    float2 v;
                    v.x = gl * (acc[i][j][0] + bb.x);
                    v.y = gl * (acc[i][j][1] + bb.y);
                    *(float2*)(g_part + (size_t)pl * DIM + n) = v;
                }
                if (ph >= 0) {
                    float2 v;
                    v.x = gh2 * (acc[i][j][2] + bb.x);
                    v.y = gh2 * (acc[i][j][3] + bb.y);
                    *(float2*)(g_part + (size_t)ph * DIM + n) = v;
                }
            }
        }
    }
}

// ---------------- kernel: combine the two slots per token ----------------
__global__ void combine_kernel(float* __restrict__ out) {
    int i = blockIdx.x * blockDim.x + threadIdx.x;
    const int total = NTOK * DIM / 4;
    if (i >= total) return;
    int n = i / (DIM / 4), d4 = i % (DIM / 4);
    const float4 a = *((const float4*)(g_part + (size_t)(2 * n)     * DIM) + d4);
    const float4 b = *((const float4*)(g_part + (size_t)(2 * n + 1) * DIM) + d4);
    float4 r; r.x = a.x + b.x; r.y = a.y + b.y; r.z = a.z + b.z; r.w = a.w + b.w;
    ((float4*)out)[i] = r;
}

// ---------------- launch ----------------
static constexpr int SMEM_BYTES = 1024 + 2 * 2 * BM * ROWB;   // 74752

extern "C" void kernel_launch(void* const* d_in, const int* in_sizes, int n_in,
                              void* d_out, int out_size) {
    const float* x  = (const float*)d_in[0];
    const float* Wg = (const float*)d_in[1];
    const float* bg = (const float*)d_in[2];
    const float* W1 = (const float*)d_in[3];
    const float* b1 = (const float*)d_in[4];
    const float* W2 = (const float*)d_in[5];
    const float* b2 = (const float*)d_in[6];
    float* out = (float*)d_out;

    cudaFuncSetAttribute(moe_mma<0, DIM, HIDDEN>,
                         cudaFuncAttributeMaxDynamicSharedMemorySize, SMEM_BYTES);
    cudaFuncSetAttribute(moe_mma<1, HIDDEN, DIM>,
                         cudaFuncAttributeMaxDynamicSharedMemorySize, SMEM_BYTES);

    __half* W1t; cudaGetSymbolAddress((void**)&W1t, g_W1t);
    __half* W2t; cudaGetSymbolAddress((void**)&W2t, g_W2t);
    __half* xh;  cudaGetSymbolAddress((void**)&xh,  g_xh);
    __half* gh;  cudaGetSymbolAddress((void**)&gh,  g_h);

    zero_cnt_kernel<<<1, 32>>>();
    gate_kernel<<<NTOK / 8, 256>>>(x, Wg, bg);
    round_x_kernel<<<(NTOK * DIM / 4 + 255) / 256, 256>>>(x);
    transpose_cvt_kernel<<<dim3(HIDDEN / 32, DIM / 32, NEXP), 256>>>(W1, W1t, DIM, HIDDEN);
    transpose_cvt_kernel<<<dim3(DIM / 32, HIDDEN / 32, NEXP), 256>>>(W2, W2t, HIDDEN, DIM);
    moe_mma<0, DIM, HIDDEN><<<dim3(NTOK / BM, HIDDEN / BN, NEXP), NT, SMEM_BYTES>>>(xh, W1t, b1);
    moe_mma<1, HIDDEN, DIM><<<dim3(NTOK / BM, DIM / BN, NEXP), NT, SMEM_BYTES>>>(gh, W2t, b2);
    combine_kernel<<<(NTOK * DIM / 4 + 255) / 256, 256>>>(out);
}